// round 14
// baseline (speedup 1.0000x reference)
#include <cuda_runtime.h>
#include <cuda.h>
#include <cstdint>

// ---------------- problem constants ----------------
#define N_ROWS  16384
#define D_IN    64
#define D_OUT   32
#define TK      32               // K per pipeline stage
#define STAGES  8
#define K_ITERS (N_ROWS / TK)    // 512

#define STAGE_A_BYTES (64 * TK * 4)          // 8192 (max: 64-row CTA)
#define STAGE_B_BYTES (2 * 32 * 20 * 4)      // 5120  ([khalf][lane][20 floats])
#define STAGE_BYTES   (STAGE_A_BYTES + STAGE_B_BYTES)   // 13312
#define SMEM_DYN      (STAGES * STAGE_BYTES + 1024)     // 107520 (x2 CTAs = 210KB)

#define NWARPS_C 4               // consumer warps: w = (mhalf<<1)|khalf
#define NTHREADS (32 * (NWARPS_C + 1))
#define GRID     296             // 2 CTAs/SM, size-matched pairs (b, b+148)

// B operand, fragment-packed for M*K-hybrid split:
//   float index = kiter*1280 + khalf*640 + lane*20 + j   (j in 0..19)
//   j = (kp*5 + nt)*2 + h -> B[k = khalf*16 + kp*8 + h*4 + (lane&3)][n = nt*8 + (lane>>2)]
__device__ float g_Bpk[K_ITERS * 1280];

// ---------------- device helpers ----------------
__device__ __forceinline__ uint32_t smem_u32(const void* p) {
    uint32_t a;
    asm("{ .reg .u64 t; cvta.to.shared.u64 t, %1; cvt.u32.u64 %0, t; }" : "=r"(a) : "l"(p));
    return a;
}
__device__ __forceinline__ float warp_sum(float v) {
    #pragma unroll
    for (int m = 16; m > 0; m >>= 1) v += __shfl_xor_sync(0xffffffffu, v, m);
    return v;
}
__device__ __forceinline__ float artanh_clip(float x) {
    x = fminf(fmaxf(x, -1.0f + 1e-7f), 1.0f - 1e-7f);
    return atanhf(x);
}
__device__ __forceinline__ float tf32_round(float x) {
    uint32_t u;
    asm("cvt.rna.tf32.f32 %0, %1;" : "=r"(u) : "f"(x));
    return __uint_as_float(u);
}
__device__ __forceinline__ void mbar_init(uint32_t mbar, uint32_t cnt) {
    asm volatile("mbarrier.init.shared.b64 [%0], %1;" :: "r"(mbar), "r"(cnt) : "memory");
}
__device__ __forceinline__ void mbar_expect_tx(uint32_t mbar, uint32_t bytes) {
    asm volatile("mbarrier.arrive.expect_tx.shared.b64 _, [%0], %1;" :: "r"(mbar), "r"(bytes) : "memory");
}
__device__ __forceinline__ void mbar_arrive(uint32_t mbar) {
    asm volatile("mbarrier.arrive.shared.b64 _, [%0];" :: "r"(mbar) : "memory");
}
__device__ __forceinline__ void mbar_wait(uint32_t mbar, uint32_t parity) {
    asm volatile(
        "{\n\t.reg .pred P;\n\t"
        "WL_%=:\n\t"
        "mbarrier.try_wait.parity.shared.b64 P, [%0], %1;\n\t"
        "@!P bra WL_%=;\n\t"
        "}" :: "r"(mbar), "r"(parity) : "memory");
}
__device__ __forceinline__ void tma_load_2d(uint32_t smem_dst, const void* tmap,
                                            int32_t cx, int32_t cy, uint32_t mbar) {
    asm volatile(
        "cp.async.bulk.tensor.2d.shared::cta.global.tile.mbarrier::complete_tx::bytes "
        "[%0], [%1, {%2, %3}], [%4];"
        :: "r"(smem_dst), "l"(tmap), "r"(cx), "r"(cy), "r"(mbar) : "memory");
}
__device__ __forceinline__ void bulk_load(uint32_t smem_dst, const void* gsrc,
                                          uint32_t bytes, uint32_t mbar) {
    asm volatile(
        "cp.async.bulk.shared::cta.global.mbarrier::complete_tx::bytes [%0], [%1], %2, [%3];"
        :: "r"(smem_dst), "l"(gsrc), "r"(bytes), "r"(mbar) : "memory");
}
__device__ __forceinline__ float lds32(uint32_t a) {
    float v;
    asm volatile("ld.shared.f32 %0, [%1];" : "=f"(v) : "r"(a));
    return v;
}
__device__ __forceinline__ void lds128(uint32_t a, uint32_t r[4]) {
    asm volatile("ld.shared.v4.u32 {%0,%1,%2,%3}, [%4];"
                 : "=r"(r[0]), "=r"(r[1]), "=r"(r[2]), "=r"(r[3]) : "r"(a));
}
__device__ __forceinline__ void lds128f(uint32_t a, float r[4]) {
    asm volatile("ld.shared.v4.f32 {%0,%1,%2,%3}, [%4];"
                 : "=f"(r[0]), "=f"(r[1]), "=f"(r[2]), "=f"(r[3]) : "r"(a));
}
__device__ __forceinline__ void sts128f(uint32_t a, const float r[4]) {
    asm volatile("st.shared.v4.f32 [%0], {%1,%2,%3,%4};"
                 :: "r"(a), "f"(r[0]), "f"(r[1]), "f"(r[2]), "f"(r[3]) : "memory");
}
__device__ __forceinline__ void mma_tf32(float c[4], uint32_t a0, uint32_t a1, uint32_t a2, uint32_t a3,
                                         uint32_t b0, uint32_t b1) {
    asm volatile(
        "mma.sync.aligned.m16n8k8.row.col.f32.tf32.tf32.f32 "
        "{%0,%1,%2,%3}, {%4,%5,%6,%7}, {%8,%9}, {%0,%1,%2,%3};"
        : "+f"(c[0]), "+f"(c[1]), "+f"(c[2]), "+f"(c[3])
        : "r"(a0), "r"(a1), "r"(a2), "r"(a3), "r"(b0), "r"(b1));
}

// ---------------- kernel 1: build fragment-packed B (hybrid-split layout) ----------------
__global__ __launch_bounds__(1024) void prep_kernel(const float* __restrict__ X,
                                                    const float* __restrict__ W) {
    __shared__ float Ws[D_IN * D_OUT];
    const int tid = threadIdx.x;
    for (int t = tid; t < D_IN * D_OUT; t += 1024) Ws[t] = W[t];
    __syncthreads();

    const int w = tid >> 5, lane = tid & 31;
    const int i = blockIdx.x * 32 + w;           // global row (= K index of B)

    const float x0 = X[i * D_IN + lane];
    const float x1 = X[i * D_IN + 32 + lane];
    const float xn = fmaxf(sqrtf(warp_sum(x0 * x0 + x1 * x1)), 1e-15f);

    float mx = 0.0f;
    #pragma unroll
    for (int k = 0; k < 32; ++k) mx = fmaf(__shfl_sync(0xffffffffu, x0, k), Ws[k * 32 + lane], mx);
    #pragma unroll
    for (int k = 0; k < 32; ++k) mx = fmaf(__shfl_sync(0xffffffffu, x1, k), Ws[(k + 32) * 32 + lane], mx);

    const float mxn = fmaxf(sqrtf(warp_sum(mx * mx)), 1e-15f);
    const float t   = tanhf((mxn / xn) * artanh_clip(xn));
    const float xw  = t * (mx / mxn);
    const float x2  = warp_sum(xw * xw);
    const float gamma = 2.0f / fmaxf(1.0f - x2, 1e-15f);

    const int k_in  = i & 31;
    const int kiter = i >> 5;
    const int ks    = k_in >> 3;
    const int khalf = ks >> 1;
    const int kp    = ks & 1;
    const int h     = (k_in >> 2) & 1;
    const int il    = k_in & 3;
    float* base = g_Bpk + (size_t)kiter * 1280 + khalf * 640;

    {   // n = lane (0..31): value xw*gamma
        const int nt = lane >> 3;
        const int tl = il | ((lane & 7) << 2);
        const int j  = (kp * 5 + nt) * 2 + h;
        base[tl * 20 + j] = tf32_round(xw * gamma);
    }
    if (lane < 2) {  // n = 32 (gamma-1), n = 33 (1.0); n=34..39 stay zero
        const float e = (lane == 0) ? (gamma - 1.0f) : 1.0f;
        const int tl = il | (lane << 2);
        const int j  = (kp * 5 + 4) * 2 + h;
        base[tl * 20 + j] = tf32_round(e);
    }
}

// ---------------- kernel 2: A @ Y, size-matched variable-TM CTAs ----------------
__global__ __launch_bounds__(NTHREADS, 2) void gemm_kernel(
    const __grid_constant__ CUtensorMap tmA64,
    const __grid_constant__ CUtensorMap tmA48,
    const float* __restrict__ Bpk,
    float* __restrict__ out)
{
    extern __shared__ uint8_t smem_dyn[];
    __shared__ __align__(8) uint64_t full_b[STAGES];
    __shared__ __align__(8) uint64_t empty_b[STAGES];

    const int tid  = threadIdx.x;
    const int wid  = tid >> 5;
    const int lane = tid & 31;

    // bid -> (row_base, ntiles): pairs (b, b+148) share an SM (wave-1 LUT placement).
    // 136 SMs get 64+48 = 112 rows; 12 SMs get 48+48 = 96 rows. 98.8% balance.
    const int b = blockIdx.x;
    int ntiles, row_base;
    if (b < 136)      { ntiles = 4; row_base = b * 64; }
    else if (b < 148) { ntiles = 3; row_base = 8704  + (b - 136) * 48; }
    else if (b < 284) { ntiles = 3; row_base = 9280  + (b - 148) * 48; }
    else              { ntiles = 3; row_base = 15808 + (b - 284) * 48; }

    const uint32_t dyn_base = (smem_u32(smem_dyn) + 1023u) & ~1023u;
    const uint32_t full0  = smem_u32(&full_b[0]);
    const uint32_t empty0 = smem_u32(&empty_b[0]);

    if (tid == 0) {
        for (int s = 0; s < STAGES; ++s) {
            mbar_init(full0 + 8u * s, 1);
            mbar_init(empty0 + 8u * s, NWARPS_C);
        }
    }
    __syncthreads();

    if (wid == NWARPS_C) {
        // -------- producer --------
        if (lane == 0) {
            const void* tmap = (ntiles == 4) ? (const void*)&tmA64 : (const void*)&tmA48;
            const uint32_t tx_bytes = (uint32_t)(2048 * ntiles) + STAGE_B_BYTES;
            uint32_t phase = 1;
            int s = 0;
            for (int it = 0; it < K_ITERS; ++it) {
                mbar_wait(empty0 + 8u * s, phase);
                const uint32_t fb = full0 + 8u * s;
                mbar_expect_tx(fb, tx_bytes);
                const uint32_t a_dst = dyn_base + (uint32_t)s * STAGE_BYTES;
                tma_load_2d(a_dst, tmap, it * TK, row_base, fb);    // A box [32 x 64|48] SW128
                bulk_load(a_dst + STAGE_A_BYTES,
                          Bpk + (size_t)it * 1280, STAGE_B_BYTES, fb);
                if (++s == STAGES) { s = 0; phase ^= 1; }
            }
        }
        return;
    }

    // -------- consumers: warp w = (mhalf<<1)|khalf --------
    const uint32_t khalf = (uint32_t)wid & 1u;
    const uint32_t mhalf = (uint32_t)wid >> 1;
    const int mtcnt = (mhalf == 0u) ? 2 : (ntiles - 2);   // m16-tiles this warp covers

    float acc[2][5][4];
    #pragma unroll
    for (int mt = 0; mt < 2; ++mt)
        #pragma unroll
        for (int nt = 0; nt < 5; ++nt)
            #pragma unroll
            for (int q = 0; q < 4; ++q) acc[mt][nt][q] = 0.0f;

    const uint32_t lane2 = lane & 3u, lane4 = lane >> 2;
    const uint32_t sw    = lane4 << 4;                            // SW128 XOR (row&7 == lane4)
    const uint32_t cb0   = khalf * 64u + lane2 * 4u;              // kp=0 byte col
    const uint32_t aoff  = (mhalf * 32u + lane4) * 128u;
    const uint32_t boff  = STAGE_A_BYTES + khalf * 2560u + lane * 80u;

    uint32_t phase = 0;
    int s = 0;
    for (int it = 0; it < K_ITERS; ++it) {
        mbar_wait(full0 + 8u * s, phase);
        const uint32_t Abase = dyn_base + (uint32_t)s * STAGE_BYTES;

        // ---- B: 5x LDS.128 (80B lane stride -> phase-conflict-free) ----
        uint32_t br[20];
        {
            const uint32_t bb = Abase + boff;
            lds128(bb,        &br[0]);
            lds128(bb + 16u,  &br[4]);
            lds128(bb + 32u,  &br[8]);
            lds128(bb + 48u,  &br[12]);
            lds128(bb + 64u,  &br[16]);
        }
        // ---- A: scalar LDS; raw fp32 bits feed tf32 mma (HW truncation, bias cancels) ----
        uint32_t au[2][2][4];
        #pragma unroll
        for (int mt = 0; mt < 2; ++mt) {
            if (mt < mtcnt) {
                const uint32_t r0 = Abase + aoff + (uint32_t)mt * 2048u;
                #pragma unroll
                for (int kp = 0; kp < 2; ++kp) {
                    const uint32_t c0 = cb0 + (uint32_t)kp * 32u;
                    au[mt][kp][0] = __float_as_uint(lds32(r0 +          (c0 ^ sw)));
                    au[mt][kp][1] = __float_as_uint(lds32(r0 + 1024u +  (c0 ^ sw)));
                    au[mt][kp][2] = __float_as_uint(lds32(r0 +         ((c0 + 16u) ^ sw)));
                    au[mt][kp][3] = __float_as_uint(lds32(r0 + 1024u + ((c0 + 16u) ^ sw)));
                }
            }
        }

        if (lane == 0) mbar_arrive(empty0 + 8u * s);   // regs hold everything

        #pragma unroll
        for (int kp = 0; kp < 2; ++kp)
            #pragma unroll
            for (int mt = 0; mt < 2; ++mt)
                if (mt < mtcnt)
                    #pragma unroll
                    for (int nt = 0; nt < 5; ++nt)
                        mma_tf32(acc[mt][nt],
                                 au[mt][kp][0], au[mt][kp][1], au[mt][kp][2], au[mt][kp][3],
                                 br[(kp * 5 + nt) * 2], br[(kp * 5 + nt) * 2 + 1]);

        if (++s == STAGES) { s = 0; phase ^= 1; }
    }

    // -------- cross-warp k-half reduction via smem (pipeline region reused) --------
    asm volatile("bar.sync 1, 128;" ::: "memory");
    {
        const uint32_t woff = dyn_base + (uint32_t)wid * 5120u + lane * 16u;
        #pragma unroll
        for (int mt = 0; mt < 2; ++mt)
            #pragma unroll
            for (int nt = 0; nt < 5; ++nt)
                sts128f(woff + (uint32_t)(mt * 5 + nt) * 512u, acc[mt][nt]);
    }
    asm volatile("bar.sync 1, 128;" ::: "memory");

    // warp w finalizes tile t = mhalf*2 + khalf (if it exists)
    const uint32_t msel    = khalf;
    const uint32_t partner = (uint32_t)wid ^ 1u;     // same mhalf, other khalf
    if ((int)(mhalf * 2u + msel) < ntiles) {
        float vsum[5][4];
        {
            const uint32_t own = dyn_base + (uint32_t)wid     * 5120u + msel * 2560u + lane * 16u;
            const uint32_t oth = dyn_base + (uint32_t)partner * 5120u + msel * 2560u + lane * 16u;
            #pragma unroll
            for (int nt = 0; nt < 5; ++nt) {
                float t0[4], t1[4];
                lds128f(own + (uint32_t)nt * 512u, t0);
                lds128f(oth + (uint32_t)nt * 512u, t1);
                #pragma unroll
                for (int q = 0; q < 4; ++q) vsum[nt][q] = t0[q] + t1[q];
            }
        }

        // -------- epilogue: hyperbolic chain per row-half --------
        #pragma unroll
        for (int h = 0; h < 2; ++h) {
            float v[8];
            #pragma unroll
            for (int nt = 0; nt < 4; ++nt) {
                v[2 * nt]     = vsum[nt][2 * h];
                v[2 * nt + 1] = vsum[nt][2 * h + 1];
            }
            float den   = __shfl_sync(0xffffffffu, vsum[4][2 * h],     lane & ~3);
            float alpha = __shfl_sync(0xffffffffu, vsum[4][2 * h + 1], lane & ~3);

            const float sgn = (den >= 0.0f) ? 1.0f : -1.0f;
            den = sgn * fmaxf(fabsf(den), 1e-10f);
            const float inv = 1.0f / den;

            float vn2 = 0.0f;
            #pragma unroll
            for (int c = 0; c < 8; ++c) { v[c] *= inv; vn2 += v[c] * v[c]; }
            vn2 += __shfl_xor_sync(0xffffffffu, vn2, 1);
            vn2 += __shfl_xor_sync(0xffffffffu, vn2, 2);

            const float vn = fmaxf(sqrtf(vn2), 1e-15f);
            const float t1 = tanhf(0.5f * artanh_clip(vn));
            const float rn = fmaxf(t1, 1e-15f);
            const float t2 = tanhf(alpha * artanh_clip(rn));
            const float xs = (t1 / vn) * (t2 / rn);
            const float xn = fmaxf(xs * vn, 1e-15f);
            const float k3 = artanh_clip(xn) / xn;
            const float us = xs * k3;

            float un2 = 0.0f;
            float u[8];
            #pragma unroll
            for (int c = 0; c < 8; ++c) { u[c] = fmaxf(v[c] * us, 0.0f); un2 += u[c] * u[c]; }
            un2 += __shfl_xor_sync(0xffffffffu, un2, 1);
            un2 += __shfl_xor_sync(0xffffffffu, un2, 2);

            const float un = fmaxf(sqrtf(un2), 1e-15f);
            const float k4 = tanhf(un) / un;

            const int row = row_base + (int)(mhalf * 32u + msel * 16u) + h * 8 + (lane >> 2);
            float* op = out + (size_t)row * D_OUT + 2 * (lane & 3);
            #pragma unroll
            for (int nt = 0; nt < 4; ++nt)
                *reinterpret_cast<float2*>(op + nt * 8) =
                    make_float2(u[2 * nt] * k4, u[2 * nt + 1] * k4);
        }
    }
}

// ---------------- host ----------------
typedef CUresult (CUDAAPI *PFN_cuTensorMapEncodeTiled_t)(
    CUtensorMap*, CUtensorMapDataType, cuuint32_t, void*,
    const cuuint64_t*, const cuuint64_t*, const cuuint32_t*, const cuuint32_t*,
    CUtensorMapInterleave, CUtensorMapSwizzle, CUtensorMapL2promotion, CUtensorMapFloatOOBfill);

extern "C" void kernel_launch(void* const* d_in, const int* in_sizes, int n_in,
                              void* d_out, int out_size) {
    const float* X = nullptr; const float* A = nullptr; const float* W = nullptr;
    for (int i = 0; i < n_in; ++i) {
        if (in_sizes[i] == N_ROWS * D_IN)     X = (const float*)d_in[i];
        else if (in_sizes[i] == D_IN * D_OUT) W = (const float*)d_in[i];
        else                                  A = (const float*)d_in[i];   // 16384^2
    }
    float* out = (float*)d_out;

    void* b_ptr = nullptr;
    cudaGetSymbolAddress(&b_ptr, g_Bpk);

    PFN_cuTensorMapEncodeTiled_t encode = nullptr;
    cudaDriverEntryPointQueryResult qr;
    cudaGetDriverEntryPointByVersion("cuTensorMapEncodeTiled", (void**)&encode,
                                     12000, cudaEnableDefault, &qr);

    CUtensorMap tmA64, tmA48;
    {   // A: [16384 x 16384] fp32, SW128; two boxes for the two CTA sizes
        cuuint64_t dims[2]    = {N_ROWS, N_ROWS};
        cuuint64_t strides[1] = {(cuuint64_t)N_ROWS * 4};
        cuuint32_t estr[2]    = {1, 1};
        cuuint32_t box64[2]   = {TK, 64};
        cuuint32_t box48[2]   = {TK, 48};
        encode(&tmA64, CU_TENSOR_MAP_DATA_TYPE_FLOAT32, 2, (void*)A,
               dims, strides, box64, estr,
               CU_TENSOR_MAP_INTERLEAVE_NONE, CU_TENSOR_MAP_SWIZZLE_128B,
               CU_TENSOR_MAP_L2_PROMOTION_L2_256B, CU_TENSOR_MAP_FLOAT_OOB_FILL_NONE);
        encode(&tmA48, CU_TENSOR_MAP_DATA_TYPE_FLOAT32, 2, (void*)A,
               dims, strides, box48, estr,
               CU_TENSOR_MAP_INTERLEAVE_NONE, CU_TENSOR_MAP_SWIZZLE_128B,
               CU_TENSOR_MAP_L2_PROMOTION_L2_256B, CU_TENSOR_MAP_FLOAT_OOB_FILL_NONE);
    }

    prep_kernel<<<N_ROWS / 32, 1024>>>(X, W);

    cudaFuncSetAttribute(gemm_kernel, cudaFuncAttributeMaxDynamicSharedMemorySize, SMEM_DYN);
    gemm_kernel<<<GRID, NTHREADS, SMEM_DYN>>>(tmA64, tmA48, (const float*)b_ptr, out);
}

// round 16
// speedup vs baseline: 1.0213x; 1.0213x over previous
#include <cuda_runtime.h>
#include <cuda.h>
#include <cstdint>

// ---------------- problem constants ----------------
#define N_ROWS  16384
#define D_IN    64
#define D_OUT   32
#define TK      32               // K per pipeline stage
#define STAGES  10
#define K_ITERS (N_ROWS / TK)    // 512

#define STAGE_A_BYTES (112 * TK * 4)         // 14336 (max: 112-row CTA)
#define STAGE_B_BYTES (2 * 32 * 20 * 4)      // 5120  ([khalf][lane][20 floats])
#define STAGE_BYTES   (STAGE_A_BYTES + STAGE_B_BYTES)   // 19456
#define SMEM_DYN      (STAGES * STAGE_BYTES + 1024)     // 195584 (1 CTA/SM)

#define NWARPS_C 8               // consumer warps: w = (mq<<1)|khalf
#define NTHREADS (32 * (NWARPS_C + 1))   // 288
#define GRID     148             // one CTA per SM -> assumption-free 98.8% balance

// B operand, fragment-packed for M*K-hybrid split:
//   float index = kiter*1280 + khalf*640 + lane*20 + j   (j in 0..19)
//   j = (kp*5 + nt)*2 + h -> B[k = khalf*16 + kp*8 + h*4 + (lane&3)][n = nt*8 + (lane>>2)]
__device__ float g_Bpk[K_ITERS * 1280];

// ---------------- device helpers ----------------
__device__ __forceinline__ uint32_t smem_u32(const void* p) {
    uint32_t a;
    asm("{ .reg .u64 t; cvta.to.shared.u64 t, %1; cvt.u32.u64 %0, t; }" : "=r"(a) : "l"(p));
    return a;
}
__device__ __forceinline__ float warp_sum(float v) {
    #pragma unroll
    for (int m = 16; m > 0; m >>= 1) v += __shfl_xor_sync(0xffffffffu, v, m);
    return v;
}
__device__ __forceinline__ float artanh_clip(float x) {
    x = fminf(fmaxf(x, -1.0f + 1e-7f), 1.0f - 1e-7f);
    return atanhf(x);
}
__device__ __forceinline__ float tf32_round(float x) {
    uint32_t u;
    asm("cvt.rna.tf32.f32 %0, %1;" : "=r"(u) : "f"(x));
    return __uint_as_float(u);
}
__device__ __forceinline__ void mbar_init(uint32_t mbar, uint32_t cnt) {
    asm volatile("mbarrier.init.shared.b64 [%0], %1;" :: "r"(mbar), "r"(cnt) : "memory");
}
__device__ __forceinline__ void mbar_expect_tx(uint32_t mbar, uint32_t bytes) {
    asm volatile("mbarrier.arrive.expect_tx.shared.b64 _, [%0], %1;" :: "r"(mbar), "r"(bytes) : "memory");
}
__device__ __forceinline__ void mbar_arrive(uint32_t mbar) {
    asm volatile("mbarrier.arrive.shared.b64 _, [%0];" :: "r"(mbar) : "memory");
}
__device__ __forceinline__ void mbar_wait(uint32_t mbar, uint32_t parity) {
    asm volatile(
        "{\n\t.reg .pred P;\n\t"
        "WL_%=:\n\t"
        "mbarrier.try_wait.parity.shared.b64 P, [%0], %1;\n\t"
        "@!P bra WL_%=;\n\t"
        "}" :: "r"(mbar), "r"(parity) : "memory");
}
__device__ __forceinline__ void tma_load_2d(uint32_t smem_dst, const void* tmap,
                                            int32_t cx, int32_t cy, uint32_t mbar) {
    asm volatile(
        "cp.async.bulk.tensor.2d.shared::cta.global.tile.mbarrier::complete_tx::bytes "
        "[%0], [%1, {%2, %3}], [%4];"
        :: "r"(smem_dst), "l"(tmap), "r"(cx), "r"(cy), "r"(mbar) : "memory");
}
__device__ __forceinline__ void bulk_load(uint32_t smem_dst, const void* gsrc,
                                          uint32_t bytes, uint32_t mbar) {
    asm volatile(
        "cp.async.bulk.shared::cta.global.mbarrier::complete_tx::bytes [%0], [%1], %2, [%3];"
        :: "r"(smem_dst), "l"(gsrc), "r"(bytes), "r"(mbar) : "memory");
}
__device__ __forceinline__ float lds32(uint32_t a) {
    float v;
    asm volatile("ld.shared.f32 %0, [%1];" : "=f"(v) : "r"(a));
    return v;
}
__device__ __forceinline__ void lds128(uint32_t a, uint32_t r[4]) {
    asm volatile("ld.shared.v4.u32 {%0,%1,%2,%3}, [%4];"
                 : "=r"(r[0]), "=r"(r[1]), "=r"(r[2]), "=r"(r[3]) : "r"(a));
}
__device__ __forceinline__ void lds128f(uint32_t a, float r[4]) {
    asm volatile("ld.shared.v4.f32 {%0,%1,%2,%3}, [%4];"
                 : "=f"(r[0]), "=f"(r[1]), "=f"(r[2]), "=f"(r[3]) : "r"(a));
}
__device__ __forceinline__ void sts128f(uint32_t a, const float r[4]) {
    asm volatile("st.shared.v4.f32 [%0], {%1,%2,%3,%4};"
                 :: "r"(a), "f"(r[0]), "f"(r[1]), "f"(r[2]), "f"(r[3]) : "memory");
}
__device__ __forceinline__ void mma_tf32(float c[4], uint32_t a0, uint32_t a1, uint32_t a2, uint32_t a3,
                                         uint32_t b0, uint32_t b1) {
    asm volatile(
        "mma.sync.aligned.m16n8k8.row.col.f32.tf32.tf32.f32 "
        "{%0,%1,%2,%3}, {%4,%5,%6,%7}, {%8,%9}, {%0,%1,%2,%3};"
        : "+f"(c[0]), "+f"(c[1]), "+f"(c[2]), "+f"(c[3])
        : "r"(a0), "r"(a1), "r"(a2), "r"(a3), "r"(b0), "r"(b1));
}

// ---------------- kernel 1: build fragment-packed B (hybrid-split layout) ----------------
__global__ __launch_bounds__(1024) void prep_kernel(const float* __restrict__ X,
                                                    const float* __restrict__ W) {
    __shared__ float Ws[D_IN * D_OUT];
    const int tid = threadIdx.x;
    for (int t = tid; t < D_IN * D_OUT; t += 1024) Ws[t] = W[t];
    __syncthreads();

    const int w = tid >> 5, lane = tid & 31;
    const int i = blockIdx.x * 32 + w;           // global row (= K index of B)

    const float x0 = X[i * D_IN + lane];
    const float x1 = X[i * D_IN + 32 + lane];
    const float xn = fmaxf(sqrtf(warp_sum(x0 * x0 + x1 * x1)), 1e-15f);

    float mx = 0.0f;
    #pragma unroll
    for (int k = 0; k < 32; ++k) mx = fmaf(__shfl_sync(0xffffffffu, x0, k), Ws[k * 32 + lane], mx);
    #pragma unroll
    for (int k = 0; k < 32; ++k) mx = fmaf(__shfl_sync(0xffffffffu, x1, k), Ws[(k + 32) * 32 + lane], mx);

    const float mxn = fmaxf(sqrtf(warp_sum(mx * mx)), 1e-15f);
    const float t   = tanhf((mxn / xn) * artanh_clip(xn));
    const float xw  = t * (mx / mxn);
    const float x2  = warp_sum(xw * xw);
    const float gamma = 2.0f / fmaxf(1.0f - x2, 1e-15f);

    const int k_in  = i & 31;
    const int kiter = i >> 5;
    const int ks    = k_in >> 3;
    const int khalf = ks >> 1;
    const int kp    = ks & 1;
    const int h     = (k_in >> 2) & 1;
    const int il    = k_in & 3;
    float* base = g_Bpk + (size_t)kiter * 1280 + khalf * 640;

    {   // n = lane (0..31): value xw*gamma
        const int nt = lane >> 3;
        const int tl = il | ((lane & 7) << 2);
        const int j  = (kp * 5 + nt) * 2 + h;
        base[tl * 20 + j] = tf32_round(xw * gamma);
    }
    if (lane < 2) {  // n = 32 (gamma-1), n = 33 (1.0); n=34..39 stay zero
        const float e = (lane == 0) ? (gamma - 1.0f) : 1.0f;
        const int tl = il | (lane << 2);
        const int j  = (kp * 5 + 4) * 2 + h;
        base[tl * 20 + j] = tf32_round(e);
    }
}

// ---------------- kernel 2: A @ Y, one CTA per SM (112|96 rows) ----------------
__global__ __launch_bounds__(NTHREADS, 1) void gemm_kernel(
    const __grid_constant__ CUtensorMap tmA112,
    const __grid_constant__ CUtensorMap tmA96,
    const float* __restrict__ Bpk,
    float* __restrict__ out)
{
    extern __shared__ uint8_t smem_dyn[];
    __shared__ __align__(8) uint64_t full_b[STAGES];
    __shared__ __align__(8) uint64_t empty_b[STAGES];

    const int tid  = threadIdx.x;
    const int wid  = tid >> 5;
    const int lane = tid & 31;

    // bid -> (row_base, ntiles): grid == 148 == #SMs, so per-SM work == per-CTA
    // work by construction (wave-1 placement is a bijection). 136x7 + 12x6 m16-tiles.
    const int b = blockIdx.x;
    const int ntiles   = (b < 136) ? 7 : 6;
    const int row_base = (b < 136) ? b * 112 : 15232 + (b - 136) * 96;

    const uint32_t dyn_base = (smem_u32(smem_dyn) + 1023u) & ~1023u;
    const uint32_t full0  = smem_u32(&full_b[0]);
    const uint32_t empty0 = smem_u32(&empty_b[0]);

    if (tid == 0) {
        for (int s = 0; s < STAGES; ++s) {
            mbar_init(full0 + 8u * s, 1);
            mbar_init(empty0 + 8u * s, NWARPS_C);
        }
    }
    __syncthreads();

    if (wid == NWARPS_C) {
        // -------- producer --------
        if (lane == 0) {
            const void* tmap = (ntiles == 7) ? (const void*)&tmA112 : (const void*)&tmA96;
            const uint32_t tx_bytes = (uint32_t)(2048 * ntiles) + STAGE_B_BYTES;
            uint32_t phase = 1;
            int s = 0;
            for (int it = 0; it < K_ITERS; ++it) {
                mbar_wait(empty0 + 8u * s, phase);
                const uint32_t fb = full0 + 8u * s;
                mbar_expect_tx(fb, tx_bytes);
                const uint32_t a_dst = dyn_base + (uint32_t)s * STAGE_BYTES;
                tma_load_2d(a_dst, tmap, it * TK, row_base, fb);    // A box [32 x 112|96] SW128
                bulk_load(a_dst + STAGE_A_BYTES,
                          Bpk + (size_t)it * 1280, STAGE_B_BYTES, fb);
                if (++s == STAGES) { s = 0; phase ^= 1; }
            }
        }
        return;
    }

    // -------- consumers: warp w = (mq<<1)|khalf; mq owns m16-tiles {2mq, 2mq+1} --------
    const uint32_t khalf = (uint32_t)wid & 1u;
    const uint32_t mq    = (uint32_t)wid >> 1;
    const int mtcnt = min(2, ntiles - 2 * (int)mq);   // 2, 1 (mq3 @7 tiles) or 0 (mq3 @6)

    float acc[2][5][4];
    #pragma unroll
    for (int mt = 0; mt < 2; ++mt)
        #pragma unroll
        for (int nt = 0; nt < 5; ++nt)
            #pragma unroll
            for (int q = 0; q < 4; ++q) acc[mt][nt][q] = 0.0f;

    const uint32_t lane2 = lane & 3u, lane4 = lane >> 2;
    const uint32_t sw    = lane4 << 4;                            // SW128 XOR (row&7 == lane4)
    const uint32_t cb0   = khalf * 64u + lane2 * 4u;              // kp=0 byte col
    const uint32_t aoff  = (mq * 32u + lane4) * 128u;
    const uint32_t boff  = STAGE_A_BYTES + khalf * 2560u + lane * 80u;

    uint32_t phase = 0;
    int s = 0;
    for (int it = 0; it < K_ITERS; ++it) {
        mbar_wait(full0 + 8u * s, phase);
        const uint32_t Abase = dyn_base + (uint32_t)s * STAGE_BYTES;

        // ---- B: 5x LDS.128 (80B lane stride -> phase-conflict-free) ----
        uint32_t br[20];
        {
            const uint32_t bb = Abase + boff;
            lds128(bb,        &br[0]);
            lds128(bb + 16u,  &br[4]);
            lds128(bb + 32u,  &br[8]);
            lds128(bb + 48u,  &br[12]);
            lds128(bb + 64u,  &br[16]);
        }
        // ---- A: scalar LDS; raw fp32 bits feed tf32 mma (HW truncation, bias cancels) ----
        uint32_t au[2][2][4];
        #pragma unroll
        for (int mt = 0; mt < 2; ++mt) {
            if (mt < mtcnt) {
                const uint32_t r0 = Abase + aoff + (uint32_t)mt * 2048u;
                #pragma unroll
                for (int kp = 0; kp < 2; ++kp) {
                    const uint32_t c0 = cb0 + (uint32_t)kp * 32u;
                    au[mt][kp][0] = __float_as_uint(lds32(r0 +          (c0 ^ sw)));
                    au[mt][kp][1] = __float_as_uint(lds32(r0 + 1024u +  (c0 ^ sw)));
                    au[mt][kp][2] = __float_as_uint(lds32(r0 +         ((c0 + 16u) ^ sw)));
                    au[mt][kp][3] = __float_as_uint(lds32(r0 + 1024u + ((c0 + 16u) ^ sw)));
                }
            }
        }

        if (lane == 0) mbar_arrive(empty0 + 8u * s);   // regs hold everything

        #pragma unroll
        for (int kp = 0; kp < 2; ++kp)
            #pragma unroll
            for (int mt = 0; mt < 2; ++mt)
                if (mt < mtcnt)
                    #pragma unroll
                    for (int nt = 0; nt < 5; ++nt)
                        mma_tf32(acc[mt][nt],
                                 au[mt][kp][0], au[mt][kp][1], au[mt][kp][2], au[mt][kp][3],
                                 br[(kp * 5 + nt) * 2], br[(kp * 5 + nt) * 2 + 1]);

        if (++s == STAGES) { s = 0; phase ^= 1; }
    }

    // -------- cross-warp k-half reduction via smem (pipeline region reused) --------
    asm volatile("bar.sync 1, %0;" :: "n"(NWARPS_C * 32) : "memory");
    {
        const uint32_t woff = dyn_base + (uint32_t)wid * 5120u + lane * 16u;
        #pragma unroll
        for (int mt = 0; mt < 2; ++mt)
            #pragma unroll
            for (int nt = 0; nt < 5; ++nt)
                sts128f(woff + (uint32_t)(mt * 5 + nt) * 512u, acc[mt][nt]);
    }
    asm volatile("bar.sync 1, %0;" :: "n"(NWARPS_C * 32) : "memory");

    // warp w finalizes tile t = 2mq + khalf (if it exists)
    const uint32_t msel    = khalf;
    const uint32_t partner = (uint32_t)wid ^ 1u;     // same mq, other khalf
    if ((int)(2u * mq + msel) < ntiles) {
        float vsum[5][4];
        {
            const uint32_t own = dyn_base + (uint32_t)wid     * 5120u + msel * 2560u + lane * 16u;
            const uint32_t oth = dyn_base + (uint32_t)partner * 5120u + msel * 2560u + lane * 16u;
            #pragma unroll
            for (int nt = 0; nt < 5; ++nt) {
                float t0[4], t1[4];
                lds128f(own + (uint32_t)nt * 512u, t0);
                lds128f(oth + (uint32_t)nt * 512u, t1);
                #pragma unroll
                for (int q = 0; q < 4; ++q) vsum[nt][q] = t0[q] + t1[q];
            }
        }

        // -------- epilogue: hyperbolic chain per row-half --------
        #pragma unroll
        for (int h = 0; h < 2; ++h) {
            float v[8];
            #pragma unroll
            for (int nt = 0; nt < 4; ++nt) {
                v[2 * nt]     = vsum[nt][2 * h];
                v[2 * nt + 1] = vsum[nt][2 * h + 1];
            }
            float den   = __shfl_sync(0xffffffffu, vsum[4][2 * h],     lane & ~3);
            float alpha = __shfl_sync(0xffffffffu, vsum[4][2 * h + 1], lane & ~3);

            const float sgn = (den >= 0.0f) ? 1.0f : -1.0f;
            den = sgn * fmaxf(fabsf(den), 1e-10f);
            const float inv = 1.0f / den;

            float vn2 = 0.0f;
            #pragma unroll
            for (int c = 0; c < 8; ++c) { v[c] *= inv; vn2 += v[c] * v[c]; }
            vn2 += __shfl_xor_sync(0xffffffffu, vn2, 1);
            vn2 += __shfl_xor_sync(0xffffffffu, vn2, 2);

            const float vn = fmaxf(sqrtf(vn2), 1e-15f);
            const float t1 = tanhf(0.5f * artanh_clip(vn));
            const float rn = fmaxf(t1, 1e-15f);
            const float t2 = tanhf(alpha * artanh_clip(rn));
            const float xs = (t1 / vn) * (t2 / rn);
            const float xn = fmaxf(xs * vn, 1e-15f);
            const float k3 = artanh_clip(xn) / xn;
            const float us = xs * k3;

            float un2 = 0.0f;
            float u[8];
            #pragma unroll
            for (int c = 0; c < 8; ++c) { u[c] = fmaxf(v[c] * us, 0.0f); un2 += u[c] * u[c]; }
            un2 += __shfl_xor_sync(0xffffffffu, un2, 1);
            un2 += __shfl_xor_sync(0xffffffffu, un2, 2);

            const float un = fmaxf(sqrtf(un2), 1e-15f);
            const float k4 = tanhf(un) / un;

            const int row = row_base + (int)(mq * 32u + msel * 16u) + h * 8 + (lane >> 2);
            float* op = out + (size_t)row * D_OUT + 2 * (lane & 3);
            #pragma unroll
            for (int nt = 0; nt < 4; ++nt)
                *reinterpret_cast<float2*>(op + nt * 8) =
                    make_float2(u[2 * nt] * k4, u[2 * nt + 1] * k4);
        }
    }
}

// ---------------- host ----------------
typedef CUresult (CUDAAPI *PFN_cuTensorMapEncodeTiled_t)(
    CUtensorMap*, CUtensorMapDataType, cuuint32_t, void*,
    const cuuint64_t*, const cuuint64_t*, const cuuint32_t*, const cuuint32_t*,
    CUtensorMapInterleave, CUtensorMapSwizzle, CUtensorMapL2promotion, CUtensorMapFloatOOBfill);

extern "C" void kernel_launch(void* const* d_in, const int* in_sizes, int n_in,
                              void* d_out, int out_size) {
    const float* X = nullptr; const float* A = nullptr; const float* W = nullptr;
    for (int i = 0; i < n_in; ++i) {
        if (in_sizes[i] == N_ROWS * D_IN)     X = (const float*)d_in[i];
        else if (in_sizes[i] == D_IN * D_OUT) W = (const float*)d_in[i];
        else                                  A = (const float*)d_in[i];   // 16384^2
    }
    float* out = (float*)d_out;

    void* b_ptr = nullptr;
    cudaGetSymbolAddress(&b_ptr, g_Bpk);

    PFN_cuTensorMapEncodeTiled_t encode = nullptr;
    cudaDriverEntryPointQueryResult qr;
    cudaGetDriverEntryPointByVersion("cuTensorMapEncodeTiled", (void**)&encode,
                                     12000, cudaEnableDefault, &qr);

    CUtensorMap tmA112, tmA96;
    {   // A: [16384 x 16384] fp32, SW128; boxes for the two CTA sizes
        cuuint64_t dims[2]    = {N_ROWS, N_ROWS};
        cuuint64_t strides[1] = {(cuuint64_t)N_ROWS * 4};
        cuuint32_t estr[2]    = {1, 1};
        cuuint32_t box112[2]  = {TK, 112};
        cuuint32_t box96[2]   = {TK, 96};
        encode(&tmA112, CU_TENSOR_MAP_DATA_TYPE_FLOAT32, 2, (void*)A,
               dims, strides, box112, estr,
               CU_TENSOR_MAP_INTERLEAVE_NONE, CU_TENSOR_MAP_SWIZZLE_128B,
               CU_TENSOR_MAP_L2_PROMOTION_L2_256B, CU_TENSOR_MAP_FLOAT_OOB_FILL_NONE);
        encode(&tmA96, CU_TENSOR_MAP_DATA_TYPE_FLOAT32, 2, (void*)A,
               dims, strides, box96, estr,
               CU_TENSOR_MAP_INTERLEAVE_NONE, CU_TENSOR_MAP_SWIZZLE_128B,
               CU_TENSOR_MAP_L2_PROMOTION_L2_256B, CU_TENSOR_MAP_FLOAT_OOB_FILL_NONE);
    }

    prep_kernel<<<N_ROWS / 32, 1024>>>(X, W);

    cudaFuncSetAttribute(gemm_kernel, cudaFuncAttributeMaxDynamicSharedMemorySize, SMEM_DYN);
    gemm_kernel<<<GRID, NTHREADS, SMEM_DYN>>>(tmA112, tmA96, (const float*)b_ptr, out);
}